// round 14
// baseline (speedup 1.0000x reference)
#include <cuda_runtime.h>
#include <cstdint>

#define NC      19
#define HW      (512 * 512)
#define NB      8
#define GX      16                   // 128 blocks, 1 per SM, one balanced wave
#define PXB     (HW / GX)            // 16384 px per block (exact)
#define THREADS 352
#define NWARP   11                   // 10 consumer warps + 1 producer warp
#define NCONS   10
#define NBINS   (NC * NC + NC)       // 380
#define NBLK    (NB * GX)            // 128
#define STPX    1024                 // pixels per stage
#define NST     (PXB / STPX)         // 16 stages
#define ST_CH_BYTES 4096u            // 1024 px * 4B per channel
#define ST_TX   (NC * ST_CH_BYTES)   // 77,824 B per stage

// Dynamic smem (float units):
//   acc [NC][NC][32] 11552 | cnt [NC][32] 608 | labw u8[PXB] 4096 words
//   stage ring: 2 x 19 x 1024 floats = 38912 | barriers: 4 x u64
#define CNT_OFF   (NC * NC * 32)               // 11552
#define LAB_OFF   (CNT_OFF + NC * 32)          // 12160
#define STAGE_OFF (LAB_OFF + PXB / 4)          // 16256 (x4B = 65,024 -> 16B aligned)
#define BAR_OFF   (STAGE_OFF + 2 * NC * STPX)  // 55168
#define SMEM_FLOATS (BAR_OFF + 16)             // 55184 floats = 220,736 B

__device__ __align__(16) float g_part[NB][NBINS][GX];
__device__ unsigned int g_count;               // zero-init; reset by finalizer

// ---- mbarrier / bulk-copy primitives -------------------------------------
__device__ __forceinline__ void mbar_init(uint32_t a, uint32_t cnt) {
    asm volatile("mbarrier.init.shared.b64 [%0], %1;" :: "r"(a), "r"(cnt) : "memory");
}
__device__ __forceinline__ void mbar_expect_tx(uint32_t a, uint32_t tx) {
    asm volatile("mbarrier.arrive.expect_tx.shared.b64 _, [%0], %1;" :: "r"(a), "r"(tx) : "memory");
}
__device__ __forceinline__ void mbar_arrive(uint32_t a) {
    asm volatile("mbarrier.arrive.shared.b64 _, [%0];" :: "r"(a) : "memory");
}
__device__ __forceinline__ void mbar_wait(uint32_t a, uint32_t ph) {
    uint32_t done;
    asm volatile("{\n\t.reg .pred p;\n\t"
        "mbarrier.try_wait.parity.acquire.cta.shared::cta.b64 p, [%1], %2;\n\t"
        "selp.b32 %0, 1, 0, p;\n\t}"
        : "=r"(done) : "r"(a), "r"(ph) : "memory");
    if (!done) {
        asm volatile("{\n\t.reg .pred P1;\n\t"
            "W_%=:\n\t"
            "mbarrier.try_wait.parity.acquire.cta.shared::cta.b64 P1, [%0], %1, 0x989680;\n\t"
            "@P1 bra.uni D_%=;\n\t"
            "bra.uni W_%=;\n\t"
            "D_%=:\n\t}" :: "r"(a), "r"(ph) : "memory");
    }
}
__device__ __forceinline__ void bulk_g2s(uint32_t dst, const void* src,
                                         uint32_t bytes, uint32_t mbar) {
    asm volatile(
        "cp.async.bulk.shared::cluster.global.mbarrier::complete_tx::bytes "
        "[%0], [%1], %2, [%3];"
        :: "r"(dst), "l"(src), "r"(bytes), "r"(mbar) : "memory");
}

__global__ __launch_bounds__(THREADS, 1)
void fused_kernel(const float* __restrict__ seg, const void* __restrict__ lab,
                  float* __restrict__ out) {
    extern __shared__ float sm[];
    float* acc = sm;
    float* cnt = sm + CNT_OFF;
    unsigned int* labw = (unsigned int*)(sm + LAB_OFF);

    const int tid  = threadIdx.x;
    const int lane = tid & 31;
    const int w    = tid >> 5;
    const int gx   = blockIdx.x;
    const int b    = blockIdx.y;

    const uint32_t sbase   = (uint32_t)__cvta_generic_to_shared(sm);
    const uint32_t stg     = sbase + STAGE_OFF * 4u;
    const uint32_t bar     = sbase + BAR_OFF * 4u;
    const uint32_t fullb[2]  = { bar,       bar + 8u  };
    const uint32_t emptyb[2] = { bar + 16u, bar + 24u };

    // Init barriers + zero accumulators.
    if (tid == 0) {
        mbar_init(fullb[0], 1);  mbar_init(fullb[1], 1);
        mbar_init(emptyb[0], NCONS); mbar_init(emptyb[1], NCONS);
    }
    for (int i = tid; i < LAB_OFF; i += THREADS) sm[i] = 0.0f;

    // Label dtype: odd 32-bit words of first 32 labels all zero <=> int64.
    int oddv = ((const int*)lab)[2 * lane + 1];
    bool is64 = (__ballot_sync(0xffffffffu, oddv != 0) == 0u);

    const long long pbase = (long long)b * HW + (long long)gx * PXB;

    // Stage labels as packed u8 (4 per u32 word).
    if (is64) {
        const longlong2* L = (const longlong2*)((const long long*)lab + pbase);
        for (int wd = tid; wd < PXB / 4; wd += THREADS) {
            longlong2 a = __ldcs(L + 2 * wd);
            longlong2 c = __ldcs(L + 2 * wd + 1);
            labw[wd] = (unsigned)a.x | ((unsigned)a.y << 8) |
                       ((unsigned)c.x << 16) | ((unsigned)c.y << 24);
        }
    } else {
        const int4* L = (const int4*)((const int*)lab + pbase);
        for (int wd = tid; wd < PXB / 4; wd += THREADS) {
            int4 a = __ldcs(L + wd);
            labw[wd] = (unsigned)a.x | ((unsigned)a.y << 8) |
                       ((unsigned)a.z << 16) | ((unsigned)a.w << 24);
        }
    }
    __syncthreads();   // barriers visible + labels staged

    if (w == NCONS) {
        // ---- Producer warp: one elected thread drives the DMA ring. ----
        if (lane == 0) {
            const float* segb = seg + (size_t)b * NC * HW + (size_t)gx * PXB;
            int pst = 0, pph = 1;                  // producer cursor (phase 1)
            for (int s = 0; s < NST; s++) {
                mbar_wait(emptyb[pst], (uint32_t)pph);
                mbar_expect_tx(fullb[pst], ST_TX);
                uint32_t dst = stg + (uint32_t)pst * ST_TX;
#pragma unroll
                for (int c = 0; c < NC; c++)
                    bulk_g2s(dst + (uint32_t)c * ST_CH_BYTES,
                             segb + (size_t)c * HW + s * STPX,
                             ST_CH_BYTES, fullb[pst]);
                if (++pst == 2) { pst = 0; pph ^= 1; }
            }
        }
    } else {
        // ---- Consumer warps ----
        if (w == NCONS - 1) {
            // Warp 9: counts over all labels (overlaps producer's stage-0 fill).
            float* cl = cnt + lane;
#pragma unroll 4
            for (int j = 0; j < PXB / 128; j++) {
                unsigned pk = labw[j * 32 + lane];
                cl[(pk & 0xffu) * 32]         += 1.0f;
                cl[((pk >> 8) & 0xffu) * 32]  += 1.0f;
                cl[((pk >> 16) & 0xffu) * 32] += 1.0f;
                cl[(pk >> 24) * 32]           += 1.0f;
            }
        }
        const int cA = (w < NCONS - 1) ? 2 * w : 18;     // channel job 1
        const int nch = (w < NCONS - 1) ? 2 : 1;         // warp 9: one channel
        float* sstg = sm + STAGE_OFF;
        int cst = 0, cph = 0;                            // consumer cursor
        for (int s = 0; s < NST; s++) {
            mbar_wait(fullb[cst], (uint32_t)cph);
            const float4* base4 = (const float4*)(sstg + cst * (NC * STPX));
            const unsigned* lw = labw + s * (STPX / 4);
#pragma unroll
            for (int ci = 0; ci < 2; ci++) {
                if (ci >= nch) break;
                const int c = cA + ci;
                const float4* cbuf = base4 + c * (STPX / 4);
                float* accc = acc + c * (NC * 32) + lane;
#pragma unroll
                for (int i = 0; i < STPX / 128; i++) {   // 8 groups
                    const int idx = i * 32 + lane;
                    float4 v = cbuf[idx];                 // LDS.128 conflict-free
                    unsigned pk = lw[idx];
                    accc[(pk & 0xffu) * 32]         += v.x;   // bank == lane
                    accc[((pk >> 8) & 0xffu) * 32]  += v.y;
                    accc[((pk >> 16) & 0xffu) * 32] += v.z;
                    accc[(pk >> 24) * 32]           += v.w;
                }
            }
            if (lane == 0) mbar_arrive(emptyb[cst]);
            if (++cst == 2) { cst = 0; cph ^= 1; }
        }
    }
    __syncthreads();

    // Reduce 32 lane columns per bin (acc and cnt contiguous; rotation -> no conflicts).
    for (int bin = tid; bin < NBINS; bin += THREADS) {
        const float* col = sm + bin * 32;
        float s = 0.0f;
#pragma unroll
        for (int j = 0; j < 32; j++) s += col[(j + tid) & 31];
        g_part[b][bin][gx] = s;
    }

    // Last-block finalize handshake.
    __threadfence();
    __syncthreads();
    __shared__ unsigned int s_last;
    if (tid == 0) s_last = atomicAdd(&g_count, 1u);
    __syncthreads();
    if (s_last != NBLK - 1) return;
    __threadfence();

    // ---- Finalize (last block) ----
    float* sS = sm;                                   // reuse smem: [NB*NBINS]
    const float4* gp4 = (const float4*)&g_part[0][0][0];
    for (int pair = tid; pair < NB * NBINS; pair += THREADS) {
        float s = 0.0f;
#pragma unroll
        for (int j = 0; j < GX / 4; j++) {            // 4 independent LDG.128
            float4 v = __ldcg(gp4 + pair * (GX / 4) + j);
            s += (v.x + v.y) + (v.z + v.w);
        }
        sS[pair] = s;
    }
    __syncthreads();

    double local = 0.0;
    for (int t2 = tid; t2 < NC * NC; t2 += THREADS) {
        const int i = t2 / NC, k = t2 % NC;
#pragma unroll
        for (int bb = 0; bb < NB; bb++) {
            const float* r = sS + bb * NBINS;
            float ci_ = r[NC * NC + i], ck = r[NC * NC + k];
            float Sii = r[i * NC + i],  Sik = r[i * NC + k];
            double alpha = (ci_ > 0.0f) ? (double)Sii / (double)ci_ : 0.0;
            double beta  = (ck  > 0.0f) ? 1.0 - (double)Sik / (double)ck : 0.0;
            local += log(0.5 * (alpha + beta + 2.220446049250313e-16));
        }
    }
#pragma unroll
    for (int o = 16; o; o >>= 1)
        local += __shfl_down_sync(0xffffffffu, local, o);
    __shared__ double ws[NWARP];
    if (lane == 0) ws[w] = local;
    __syncthreads();
    if (tid == 0) {
        double tot = 0.0;
#pragma unroll
        for (int j = 0; j < NWARP; j++) tot += ws[j];
        out[0] = (float)(-0.5 * tot / (double)NB);
        g_count = 0u;                                 // reset for next graph replay
    }
}

extern "C" void kernel_launch(void* const* d_in, const int* in_sizes, int n_in,
                              void* d_out, int out_size) {
    const float* seg = (const float*)d_in[0];
    const void*  lab = d_in[1];
    float* out = (float*)d_out;

    const int smem = SMEM_FLOATS * sizeof(float);     // 220,736 B
    (void)cudaFuncSetAttribute(fused_kernel,
                               cudaFuncAttributeMaxDynamicSharedMemorySize, smem);

    dim3 grid(GX, NB);
    fused_kernel<<<grid, THREADS, smem>>>(seg, lab, out);
}

// round 17
// speedup vs baseline: 1.1205x; 1.1205x over previous
#include <cuda_runtime.h>
#include <cstdint>

#define NC      19
#define HW      (512 * 512)
#define NB      8
#define GX      16                    // 128 blocks, 1/SM, single wave
#define PXB     (HW / GX)             // 16384 px per block
#define THREADS 320
#define NWARP   10
#define NG      5                     // channel groups of 4 (group 4 = 3ch + count)
#define NH      2                     // pixel halves
#define HPX     (PXB / NH)            // 8192 px per warp
#define STPX    128                   // px per stage per warp
#define NST     (HPX / STPX)          // 64 stages
#define NBINS   (NC * NC + NC)        // 380
#define NBLK    (NB * GX)             // 128

// smem float layout:
//   ACC [19][5][2][32][4] : 24320 floats (97,280 B), float4 cells, single-owner
//   LABW u32[4096]        :  4096 words (16,384 B)  packed u8 labels
//   STG [10 warps][2 st][4 ch][128 px] : 10240 floats (40,960 B)
#define LABW_OFF 24320
#define STG_OFF  (LABW_OFF + PXB / 4)            // 28416
#define SMEM_FLOATS (STG_OFF + NWARP * 1024)     // 38656 floats = 154,624 B

__device__ __align__(16) float g_part[NB][NBINS][GX];
__device__ unsigned int g_count;                 // zero-init; reset by finalizer

__device__ __forceinline__ void cpasync16(uint32_t dst, const void* src) {
    asm volatile("cp.async.cg.shared.global [%0], [%1], 16;" :: "r"(dst), "l"(src) : "memory");
}
__device__ __forceinline__ void cpcommit() {
    asm volatile("cp.async.commit_group;" ::: "memory");
}
__device__ __forceinline__ void cpwait1() { asm volatile("cp.async.wait_group 1;" ::: "memory"); }
__device__ __forceinline__ void cpwait0() { asm volatile("cp.async.wait_group 0;" ::: "memory"); }

__global__ __launch_bounds__(THREADS, 1)
void fused_kernel(const float* __restrict__ seg, const void* __restrict__ lab,
                  float* __restrict__ out) {
    extern __shared__ float sm[];
    unsigned int* labw = (unsigned int*)(sm + LABW_OFF);

    const int tid  = threadIdx.x;
    const int lane = tid & 31;
    const int w    = tid >> 5;
    const int gx   = blockIdx.x;
    const int b    = blockIdx.y;

    // Zero ACC (labels/staging fully overwritten).
    for (int i = tid; i < LABW_OFF; i += THREADS) sm[i] = 0.0f;

    // Label dtype: odd 32-bit words of first 32 labels all zero <=> int64.
    int oddv = ((const int*)lab)[2 * lane + 1];
    bool is64 = (__ballot_sync(0xffffffffu, oddv != 0) == 0u);

    const long long pbase = (long long)b * HW + (long long)gx * PXB;

    // Stage labels as packed u8 (4 per u32 word).
    if (is64) {
        const longlong2* L = (const longlong2*)((const long long*)lab + pbase);
        for (int wd = tid; wd < PXB / 4; wd += THREADS) {
            longlong2 a = __ldcs(L + 2 * wd);
            longlong2 c = __ldcs(L + 2 * wd + 1);
            labw[wd] = (unsigned)a.x | ((unsigned)a.y << 8) |
                       ((unsigned)c.x << 16) | ((unsigned)c.y << 24);
        }
    } else {
        const int4* L = (const int4*)((const int*)lab + pbase);
        for (int wd = tid; wd < PXB / 4; wd += THREADS) {
            int4 a = __ldcs(L + wd);
            labw[wd] = (unsigned)a.x | ((unsigned)a.y << 8) |
                       ((unsigned)a.z << 16) | ((unsigned)a.w << 24);
        }
    }
    __syncthreads();

    // ---- Per-warp independent pipeline: warp w -> group g, pixel-half h. ----
    const int g = w % NG;
    const int h = w / NG;
    const int nch = (g < NG - 1) ? 4 : 3;            // group 4: 3 channels + count
    const float* segb = seg + (size_t)b * NC * HW + (size_t)gx * PXB + (size_t)h * HPX;
    float* stg = sm + STG_OFF + w * 1024;            // [2][4][128] floats
    const uint32_t stga = (uint32_t)__cvta_generic_to_shared(stg);
    // float4 view of ACC: cell index ((k*5+g)*2+h)*32 + lane
    float4* a4base = (float4*)sm + (g * 2 + h) * 32 + lane;

    // prologue: stages 0,1
#pragma unroll
    for (int s = 0; s < 2; s++) {
        uint32_t dst = stga + (unsigned)(s * 512) * 4u + (unsigned)lane * 16u;
#pragma unroll
        for (int c = 0; c < 4; c++)
            if (c < nch) cpasync16(dst + c * 512u,
                                   segb + (size_t)(g * 4 + c) * HW + s * STPX + lane * 4);
        cpcommit();
    }

    for (int s = 0; s < NST; s++) {
        if (s == NST - 1) cpwait0(); else cpwait1(); // stage s landed
        const float* buf = stg + (s & 1) * 512;

        // Preload all values + labels for this stage (no STS in the way -> pipelined).
        float v[4][4];                               // [element i][channel slot]
        int   kk[4];
#pragma unroll
        for (int i = 0; i < 4; i++) {
            const int px = i * 32 + lane;
#pragma unroll
            for (int c = 0; c < 4; c++)
                v[i][c] = (c < nch) ? buf[c * 128 + px] : 1.0f;   // slot3 of g4 = count
            unsigned wdid = (unsigned)(h * (HPX / 4) + s * 32 + i * 8 + (lane >> 2));
            kk[i] = (int)((labw[wdid] >> ((lane & 3) * 8)) & 0xffu);
        }
        // 4 RMW chain elements, each covering 4 channel-sums.
#pragma unroll
        for (int i = 0; i < 4; i++) {
            float4* a4 = a4base + kk[i] * (NG * NH * 32);
            float4 o = *a4;
            o.x += v[i][0]; o.y += v[i][1]; o.z += v[i][2]; o.w += v[i][3];
            *a4 = o;
        }
        if (s + 2 < NST) {                           // refill this slot
            uint32_t dst = stga + (unsigned)((s & 1) * 512) * 4u + (unsigned)lane * 16u;
#pragma unroll
            for (int c = 0; c < 4; c++)
                if (c < nch) cpasync16(dst + c * 512u,
                                       segb + (size_t)(g * 4 + c) * HW + (s + 2) * STPX + lane * 4);
            cpcommit();
        }
    }
    __syncthreads();

    // ---- Reduce: bin (c,k) = sum over halves and 32 lanes. ----
    for (int bin = tid; bin < NBINS; bin += THREADS) {
        int k, gg, slot;
        if (bin < NC * NC) { int c = bin / NC; k = bin % NC; gg = c >> 2; slot = c & 3; }
        else               { k = bin - NC * NC; gg = 4; slot = 3; }
        float s = 0.0f;
#pragma unroll
        for (int hh = 0; hh < NH; hh++) {
            const float* base = sm + (((k * NG + gg) * NH + hh) * 32) * 4 + slot;
#pragma unroll 8
            for (int jj = 0; jj < 32; jj++) {
                int j = (jj + tid) & 31;             // rotate -> spread banks
                s += base[j * 4];
            }
        }
        g_part[b][bin][gx] = s;
    }

    // Last-block finalize handshake.
    __threadfence();
    __syncthreads();
    __shared__ unsigned int s_last;
    if (tid == 0) s_last = atomicAdd(&g_count, 1u);
    __syncthreads();
    if (s_last != NBLK - 1) return;
    __threadfence();

    // ---- Finalize (last block) ----
    float* sS = sm;                                  // reuse: [NB*NBINS] floats
    const float4* gp4 = (const float4*)&g_part[0][0][0];
    for (int pair = tid; pair < NB * NBINS; pair += THREADS) {
        float s = 0.0f;
#pragma unroll
        for (int j = 0; j < GX / 4; j++) {
            float4 vv = __ldcg(gp4 + pair * (GX / 4) + j);
            s += (vv.x + vv.y) + (vv.z + vv.w);
        }
        sS[pair] = s;
    }
    __syncthreads();

    double local = 0.0;
    for (int t2 = tid; t2 < NC * NC; t2 += THREADS) {
        const int i = t2 / NC, k = t2 % NC;
#pragma unroll
        for (int bb = 0; bb < NB; bb++) {
            const float* r = sS + bb * NBINS;
            float ci_ = r[NC * NC + i], ck = r[NC * NC + k];
            float Sii = r[i * NC + i],  Sik = r[i * NC + k];
            double alpha = (ci_ > 0.0f) ? (double)Sii / (double)ci_ : 0.0;
            double beta  = (ck  > 0.0f) ? 1.0 - (double)Sik / (double)ck : 0.0;
            local += log(0.5 * (alpha + beta + 2.220446049250313e-16));
        }
    }
#pragma unroll
    for (int o = 16; o; o >>= 1)
        local += __shfl_down_sync(0xffffffffu, local, o);
    __shared__ double ws[NWARP];
    if (lane == 0) ws[w] = local;
    __syncthreads();
    if (tid == 0) {
        double tot = 0.0;
#pragma unroll
        for (int j = 0; j < NWARP; j++) tot += ws[j];
        out[0] = (float)(-0.5 * tot / (double)NB);
        g_count = 0u;                                // reset for next graph replay
    }
}

extern "C" void kernel_launch(void* const* d_in, const int* in_sizes, int n_in,
                              void* d_out, int out_size) {
    const float* seg = (const float*)d_in[0];
    const void*  lab = d_in[1];
    float* out = (float*)d_out;

    const int smem = SMEM_FLOATS * sizeof(float);    // 154,624 B
    (void)cudaFuncSetAttribute(fused_kernel,
                               cudaFuncAttributeMaxDynamicSharedMemorySize, smem);

    dim3 grid(GX, NB);
    fused_kernel<<<grid, THREADS, smem>>>(seg, lab, out);
}